// round 9
// baseline (speedup 1.0000x reference)
#include <cuda_runtime.h>

#define D 128
#define MAXN 40000
#define MAXE 640000

// ---------------- scratch (static device globals; no allocation) -------------
__device__ float g_deg[MAXN];
__device__ int   g_cnt[MAXN];
__device__ int   g_offs[MAXN + 1];
__device__ int   g_cursor[MAXN];
__device__ int   g_srcs[MAXE];
__device__ float g_nrm[MAXE];
__device__ __align__(16) float g_H[MAXN * D];   // h = X @ W (current layer)
__device__ __align__(16) float g_G[MAXN * D];   // post-agg activations
__device__ int   g_is64;                        // edge_index dtype flag

// ---------------- f32x2 packed-FMA helpers ------------------------------------
__device__ __forceinline__ unsigned long long pack2(float lo, float hi) {
    unsigned long long d;
    asm("mov.b64 %0, {%1, %2};" : "=l"(d) : "f"(lo), "f"(hi));
    return d;
}
__device__ __forceinline__ void unpack2(unsigned long long v, float& lo, float& hi) {
    asm("mov.b64 {%0, %1}, %2;" : "=f"(lo), "=f"(hi) : "l"(v));
}
__device__ __forceinline__ unsigned long long fma2(unsigned long long a,
                                                   unsigned long long b,
                                                   unsigned long long c) {
    unsigned long long d;
    asm("fma.rn.f32x2 %0, %1, %2, %3;" : "=l"(d) : "l"(a), "l"(b), "l"(c));
    return d;
}

// ---------------- init + dtype probe ------------------------------------------
__global__ void k_init(const void* __restrict__ ei, int n) {
    int i = blockIdx.x * blockDim.x + threadIdx.x;
    if (i < n) { g_deg[i] = 1.0f; g_cnt[i] = 0; }   // 1.0 = self-loop weight
    if (blockIdx.x == 0) {
        const long long* p = (const long long*)ei;
        bool bad = false;
        for (int j = threadIdx.x; j < 1024; j += blockDim.x) {
            long long v = p[j];
            if (v < 0 || v >= MAXN) bad = true;
        }
        bad = __syncthreads_or(bad);
        if (threadIdx.x == 0) g_is64 = bad ? 0 : 1;
    }
}

__device__ __forceinline__ int edge_at(const void* ei, long long idx) {
    if (g_is64) return (int)((const long long*)ei)[idx];
    return ((const int*)ei)[idx];
}

__global__ void k_deg(const void* __restrict__ ei,
                      const float* __restrict__ ea, int e) {
    int i = blockIdx.x * blockDim.x + threadIdx.x;
    if (i < e) {
        int dst = edge_at(ei, (long long)e + i);
        atomicAdd(&g_deg[dst], ea[i]);
        atomicAdd(&g_cnt[dst], 1);
    }
}

// Single-block exclusive scan of g_cnt -> g_offs / g_cursor (n <= 40960)
__global__ void k_scan(int n) {
    __shared__ int s[1024];
    int t = threadIdx.x;
    int ch = (n + 1023) >> 10;
    int base = t * ch;
    int sum = 0;
    for (int j = 0; j < ch; j++) {
        int idx = base + j;
        if (idx < n) sum += g_cnt[idx];
    }
    s[t] = sum;
    __syncthreads();
    for (int off = 1; off < 1024; off <<= 1) {
        int v = (t >= off) ? s[t - off] : 0;
        __syncthreads();
        s[t] += v;
        __syncthreads();
    }
    if (t == 1023) g_offs[n] = s[1023];
    int prefix = (t == 0) ? 0 : s[t - 1];
    for (int j = 0; j < ch; j++) {
        int idx = base + j;
        if (idx < n) {
            g_offs[idx]   = prefix;
            g_cursor[idx] = prefix;
            prefix += g_cnt[idx];
        }
    }
}

__global__ void k_fill(const void* __restrict__ ei,
                       const float* __restrict__ ea, int e) {
    int i = blockIdx.x * blockDim.x + threadIdx.x;
    if (i < e) {
        int src = edge_at(ei, i);
        int dst = edge_at(ei, (long long)e + i);
        int pos = atomicAdd(&g_cursor[dst], 1);
        g_srcs[pos] = src;
        g_nrm[pos]  = rsqrtf(g_deg[src]) * ea[i] * rsqrtf(g_deg[dst]);
    }
}

// ---------------- SGEMM (f32x2, double-buffered): g_H = A @ W ----------------
// 256 threads, 64x128 tile, BK=16, ping-pong smem. Thread = 4 rows x 8 cols,
// rows packed pairwise into fma.rn.f32x2 accumulators. Next k-tile LDGs issue
// before the current tile's math -> global latency fully hidden; 1 sync/iter.
template <int USE_G>
__global__ void __launch_bounds__(256) k_gemm(const float* __restrict__ Ain,
                                              const float* __restrict__ W,
                                              int nrows) {
    const float* __restrict__ A = USE_G ? (const float*)g_G : Ain;
    __shared__ __align__(16) float xs_t[2][16][66];   // [buf][k][row] (transposed)
    __shared__ __align__(16) float ws[2][16][128];    // [buf][k][col]
    int tid = threadIdx.x;
    int tx = tid & 15;      // cols tx*8 .. tx*8+7
    int ty = tid >> 4;      // rows ty*4 .. ty*4+3 (2 packed pairs)
    int row0 = blockIdx.x * 64;

    // X load mapping: thread -> (row = tid>>2, 4-wide k segment)
    int lrow = tid >> 2;
    int lseg = (tid & 3) * 4;
    int grow = row0 + lrow;
    if (grow >= nrows) grow = nrows - 1;
    const float* aptr = &A[grow * D + lseg];

    // W load mapping: rows wr0 and wr0+8, same 4-wide col segment
    int wr0 = tid >> 5;
    int wc0 = (tid & 31) * 4;

    unsigned long long acc[2][8];
#pragma unroll
    for (int m = 0; m < 2; m++)
#pragma unroll
        for (int nn = 0; nn < 8; nn++) acc[m][nn] = 0ull;

    // prologue: load tile 0
    float4 xv  = *(const float4*)aptr;
    float4 wv0 = *(const float4*)&W[wr0 * D + wc0];
    float4 wv1 = *(const float4*)&W[(wr0 + 8) * D + wc0];
    xs_t[0][lseg + 0][lrow] = xv.x; xs_t[0][lseg + 1][lrow] = xv.y;
    xs_t[0][lseg + 2][lrow] = xv.z; xs_t[0][lseg + 3][lrow] = xv.w;
    *(float4*)&ws[0][wr0][wc0]     = wv0;
    *(float4*)&ws[0][wr0 + 8][wc0] = wv1;
    __syncthreads();

#pragma unroll
    for (int it = 0; it < 8; it++) {
        int cur = it & 1;
        int nxt = cur ^ 1;
        if (it < 7) {                       // prefetch next k-tile into regs
            int k0 = (it + 1) * 16;
            xv  = *(const float4*)(aptr + k0);
            wv0 = *(const float4*)&W[(k0 + wr0) * D + wc0];
            wv1 = *(const float4*)&W[(k0 + wr0 + 8) * D + wc0];
        }
#pragma unroll
        for (int kk = 0; kk < 16; kk++) {
            unsigned long long rm0 =
                *(const unsigned long long*)&xs_t[cur][kk][ty * 4];
            unsigned long long rm1 =
                *(const unsigned long long*)&xs_t[cur][kk][ty * 4 + 2];
            float4 fa = *(const float4*)&ws[cur][kk][tx * 8];
            float4 fb = *(const float4*)&ws[cur][kk][tx * 8 + 4];
            unsigned long long rnb[8];
            rnb[0] = pack2(fa.x, fa.x); rnb[1] = pack2(fa.y, fa.y);
            rnb[2] = pack2(fa.z, fa.z); rnb[3] = pack2(fa.w, fa.w);
            rnb[4] = pack2(fb.x, fb.x); rnb[5] = pack2(fb.y, fb.y);
            rnb[6] = pack2(fb.z, fb.z); rnb[7] = pack2(fb.w, fb.w);
#pragma unroll
            for (int nn = 0; nn < 8; nn++) {
                acc[0][nn] = fma2(rm0, rnb[nn], acc[0][nn]);
                acc[1][nn] = fma2(rm1, rnb[nn], acc[1][nn]);
            }
        }
        if (it < 7) {                       // commit prefetched tile, 1 sync
            xs_t[nxt][lseg + 0][lrow] = xv.x; xs_t[nxt][lseg + 1][lrow] = xv.y;
            xs_t[nxt][lseg + 2][lrow] = xv.z; xs_t[nxt][lseg + 3][lrow] = xv.w;
            *(float4*)&ws[nxt][wr0][wc0]     = wv0;
            *(float4*)&ws[nxt][wr0 + 8][wc0] = wv1;
            __syncthreads();
        }
    }

    // epilogue: unpack row pairs, two float4 stores per row
#pragma unroll
    for (int m = 0; m < 2; m++) {
        float lo[8], hi[8];
#pragma unroll
        for (int nn = 0; nn < 8; nn++) unpack2(acc[m][nn], lo[nn], hi[nn]);
        int r_lo = row0 + ty * 4 + 2 * m;
        int r_hi = r_lo + 1;
        int c = tx * 8;
        if (r_lo < nrows) {
            *(float4*)&g_H[r_lo * D + c]     = make_float4(lo[0], lo[1], lo[2], lo[3]);
            *(float4*)&g_H[r_lo * D + c + 4] = make_float4(lo[4], lo[5], lo[6], lo[7]);
        }
        if (r_hi < nrows) {
            *(float4*)&g_H[r_hi * D + c]     = make_float4(hi[0], hi[1], hi[2], hi[3]);
            *(float4*)&g_H[r_hi * D + c + 4] = make_float4(hi[4], hi[5], hi[6], hi[7]);
        }
    }
}

// ---------------- aggregation: warp per node, float4 per lane ----------------
template <int LN>
__global__ void k_agg(const float* __restrict__ bias,
                      const float* __restrict__ gamma, const float* __restrict__ beta,
                      float* __restrict__ outp, int n) {
    int w = (blockIdx.x * blockDim.x + threadIdx.x) >> 5;
    int lane = threadIdx.x & 31;
    if (w >= n) return;

    const float4* __restrict__ H4 = (const float4*)g_H;
    float di = rsqrtf(g_deg[w]);
    float selfw = di * di;
    float4 h = __ldg(&H4[w * 32 + lane]);
    float4 acc = make_float4(h.x * selfw, h.y * selfw, h.z * selfw, h.w * selfw);

    int ib = g_offs[w];
    int ie = g_offs[w + 1];
    int i = ib;
    for (; i + 4 <= ie; i += 4) {
        int   s0 = g_srcs[i],     s1 = g_srcs[i + 1];
        int   s2 = g_srcs[i + 2], s3 = g_srcs[i + 3];
        float w0 = g_nrm[i],      w1 = g_nrm[i + 1];
        float w2 = g_nrm[i + 2],  w3 = g_nrm[i + 3];
        float4 a = __ldg(&H4[s0 * 32 + lane]);
        float4 b = __ldg(&H4[s1 * 32 + lane]);
        float4 c = __ldg(&H4[s2 * 32 + lane]);
        float4 d = __ldg(&H4[s3 * 32 + lane]);
        acc.x += a.x * w0; acc.y += a.y * w0; acc.z += a.z * w0; acc.w += a.w * w0;
        acc.x += b.x * w1; acc.y += b.y * w1; acc.z += b.z * w1; acc.w += b.w * w1;
        acc.x += c.x * w2; acc.y += c.y * w2; acc.z += c.z * w2; acc.w += c.w * w2;
        acc.x += d.x * w3; acc.y += d.y * w3; acc.z += d.z * w3; acc.w += d.w * w3;
    }
    for (; i < ie; i++) {
        int s0 = g_srcs[i];
        float w0 = g_nrm[i];
        float4 a = __ldg(&H4[s0 * 32 + lane]);
        acc.x += a.x * w0; acc.y += a.y * w0; acc.z += a.z * w0; acc.w += a.w * w0;
    }

    float4 b4 = ((const float4*)bias)[lane];
    acc.x = fmaxf(acc.x + b4.x, 0.0f);
    acc.y = fmaxf(acc.y + b4.y, 0.0f);
    acc.z = fmaxf(acc.z + b4.z, 0.0f);
    acc.w = fmaxf(acc.w + b4.w, 0.0f);

    if (LN) {
        float s1 = acc.x + acc.y + acc.z + acc.w;
#pragma unroll
        for (int o = 16; o > 0; o >>= 1)
            s1 += __shfl_xor_sync(0xffffffffu, s1, o);
        float mu = s1 * (1.0f / 128.0f);
        float dx = acc.x - mu, dy = acc.y - mu, dz = acc.z - mu, dw = acc.w - mu;
        float s2 = dx * dx + dy * dy + dz * dz + dw * dw;
#pragma unroll
        for (int o = 16; o > 0; o >>= 1)
            s2 += __shfl_xor_sync(0xffffffffu, s2, o);
        float r = rsqrtf(s2 * (1.0f / 128.0f) + 1e-5f);
        float4 g4  = ((const float4*)gamma)[lane];
        float4 be4 = ((const float4*)beta)[lane];
        acc.x = dx * r * g4.x + be4.x;
        acc.y = dy * r * g4.y + be4.y;
        acc.z = dz * r * g4.z + be4.z;
        acc.w = dw * r * g4.w + be4.w;
        ((float4*)outp)[w * 32 + lane] = acc;
    } else {
        ((float4*)g_G)[w * 32 + lane] = acc;
    }
}

// ---------------- launch ------------------------------------------------------
extern "C" void kernel_launch(void* const* d_in, const int* in_sizes, int n_in,
                              void* d_out, int out_size) {
    const float* x   = (const float*)d_in[0];
    const void*  ei  = d_in[1];
    const float* ea  = (const float*)d_in[2];
    const float* W1  = (const float*)d_in[3];
    const float* b1  = (const float*)d_in[4];
    const float* W2  = (const float*)d_in[5];
    const float* b2  = (const float*)d_in[6];
    const float* lng = (const float*)d_in[7];
    const float* lnb = (const float*)d_in[8];

    int n = in_sizes[0] / D;   // 40000
    int e = in_sizes[2];       // 640000

    int nb = (n + 255) / 256;
    int eb = (e + 255) / 256;

    // CSR + norm build (pure function of inputs every call)
    k_init<<<nb, 256>>>(ei, n);
    k_deg<<<eb, 256>>>(ei, ea, e);
    k_scan<<<1, 1024>>>(n);
    k_fill<<<eb, 256>>>(ei, ea, e);

    int gemm_blocks = (n + 63) / 64;
    int agg_blocks  = (n * 32 + 255) / 256;

    // layer 1: H = x @ W1 ; G = relu(agg(H) + b1)
    k_gemm<0><<<gemm_blocks, 256>>>(x, W1, n);
    k_agg<0><<<agg_blocks, 256>>>(b1, nullptr, nullptr, nullptr, n);
    // layer 2: H = G @ W2 ; out = LN(relu(agg(H) + b2))
    k_gemm<1><<<gemm_blocks, 256>>>(nullptr, W2, n);
    k_agg<1><<<agg_blocks, 256>>>(b2, lng, lnb, (float*)d_out, n);
}